// round 1
// baseline (speedup 1.0000x reference)
#include <cuda_runtime.h>

#define L_TOT    524288
#define M_TOT    (L_TOT / 4)     // 131072 subband samples
#define NBATCH   16
#define TILE     2048
#define NTILES   (L_TOT / TILE)  // 256
#define THREADS  256
#define PH_SZ    560             // per-phase smem stride (max swz index 559)
#define YP_SZ    528             // staging: swz(511)=526

// combined polyphase filters: C[r][dd], dd = d+64 in [0,128]
__device__ float g_C[4][132];

__device__ __forceinline__ int swz(int i) { return i + (i >> 5); }

__global__ void build_C_kernel(const float* __restrict__ qmf) {
    int idx = blockIdx.x * blockDim.x + threadIdx.x;
    if (idx >= 4 * 129) return;
    int r  = idx / 129;
    int dd = idx % 129;          // dd = d + 64
    int t0 = (4 - r) & 3;        // t == (-n) mod 4 for n == r (mod 4)
    float sum = 0.f;
    for (int t = t0; t <= 64; t += 4) {
        int s = dd - t;          // s = d - t + 64
        if (s >= 0 && s <= 64) {
            #pragma unroll
            for (int k = 0; k < 4; k++)
                sum += qmf[k * 65 + t] * qmf[k * 65 + s];
        }
    }
    g_C[r][dd] = sum;
}

__global__ __launch_bounds__(THREADS)
void pqmf_fused_kernel(const float* __restrict__ x,
                       const float* __restrict__ qmf,
                       float* __restrict__ y) {
    __shared__ float s_xp[4][PH_SZ];   // phase-split x tile with 64-halo
    __shared__ float s_C[4][132];
    __shared__ float s_yp[4][YP_SZ];   // phase-split output staging
    __shared__ float s_part[128];

    const int tile  = blockIdx.x;
    const int b     = blockIdx.y;
    const int tbase = tile * TILE;
    const float* xb = x + (size_t)b * L_TOT;
    float*       yb = y + (size_t)b * L_TOT;

    // ---- load x[tbase-64 .. tbase+TILE+64) into phase-split smem (0-padded) ----
    for (int idx = threadIdx.x; idx < TILE + 128; idx += THREADS) {
        int pos = tbase - 64 + idx;
        float v = (pos >= 0 && pos < L_TOT) ? xb[pos] : 0.f;
        s_xp[idx & 3][swz(idx >> 2)] = v;
    }
    for (int idx = threadIdx.x; idx < 4 * 129; idx += THREADS)
        s_C[idx / 129][idx % 129] = g_C[idx / 129][idx % 129];
    __syncthreads();

    const int warp = threadIdx.x >> 5;
    const int lane = threadIdx.x & 31;
    const int r    = warp & 3;                  // residue owned by this warp
    const int tq   = (warp >> 2) * 32 + lane;   // 0..63 per residue
    const int base_q = tq * 8;                  // 8 contiguous outputs per thread

    float acc[8];
    #pragma unroll
    for (int j = 0; j < 8; j++) acc[j] = 0.f;

    // y[r+4q] = sum_{dd=0..128} C_r[dd] * sx[(r+4q) + dd], split dd = 4e+f
    #pragma unroll
    for (int f = 0; f < 4; f++) {
        const int E  = (f == 0) ? 33 : 32;
        const int rf = r + f;
        const int p  = rf & 3;
        const int i0 = base_q + (rf >> 2);
        const float* xr = s_xp[p];
        const float* cr = &s_C[r][f];

        float w[8];
        #pragma unroll
        for (int j = 0; j < 7; j++) w[j] = xr[swz(i0 + j)];

        #pragma unroll
        for (int e = 0; e < 33; e++) {
            if (e < E) {
                float c = cr[4 * e];                // warp-uniform broadcast
                w[7] = xr[swz(i0 + e + 7)];
                #pragma unroll
                for (int j = 0; j < 8; j++) acc[j] = fmaf(c, w[j], acc[j]);
                #pragma unroll
                for (int j = 0; j < 7; j++) w[j] = w[j + 1];
            }
        }
    }

    // ---- stage outputs (phase-split, conflict-free) then coalesced store ----
    #pragma unroll
    for (int j = 0; j < 8; j++)
        s_yp[r][swz(base_q + j)] = acc[j];
    __syncthreads();

    for (int idx = threadIdx.x; idx < TILE; idx += THREADS) {
        int n = tbase + idx;
        float v = s_yp[idx & 3][swz(idx >> 2)];
        if (n >= 32 && n < L_TOT - 32)   // edge samples handled exactly below
            yb[n] = v;
    }

    // ---- exact two-stage path for the 32 edge samples at each end ----
    const bool lo_edge = (tile == 0);
    const bool hi_edge = (tile == NTILES - 1);
    if (lo_edge || hi_edge) {
        const int task = threadIdx.x;
        float partial = 0.f;
        if (task < 128) {
            const int nn = task >> 2;
            const int k  = task & 3;
            const int n  = lo_edge ? nn : (L_TOT - 32 + nn);
            const int t0 = (4 - (n & 3)) & 3;
            for (int t = t0; t <= 64; t += 4) {
                int m = (n + t - 32) >> 2;          // exact (divisible by 4)
                if (m < 0 || m >= M_TOT) continue;
                float sub = 0.f;
                int pbase = 4 * m - 32;
                for (int s = 0; s <= 64; s++) {
                    int pos = pbase + s;
                    if (pos >= 0 && pos < L_TOT) {
                        int g = pos - tbase + 64;   // in-tile (halo covers it)
                        sub = fmaf(qmf[k * 65 + s],
                                   s_xp[g & 3][swz(g >> 2)], sub);
                    }
                }
                partial = fmaf(qmf[k * 65 + t], sub, partial);
            }
        }
        __syncthreads();
        if (task < 128) s_part[task] = partial;
        __syncthreads();
        if (task < 32) {
            int n = lo_edge ? task : (L_TOT - 32 + task);
            yb[n] = s_part[task * 4] + s_part[task * 4 + 1] +
                    s_part[task * 4 + 2] + s_part[task * 4 + 3];
        }
    }
}

extern "C" void kernel_launch(void* const* d_in, const int* in_sizes, int n_in,
                              void* d_out, int out_size) {
    // inputs: x (16*1*524288 f32), qmf (4*65 f32) — detect order defensively
    const float* x   = (const float*)d_in[0];
    const float* qmf = (const float*)d_in[1];
    if (n_in >= 2 && in_sizes[0] == 260) {
        x   = (const float*)d_in[1];
        qmf = (const float*)d_in[0];
    }
    float* y = (float*)d_out;

    build_C_kernel<<<3, 192>>>(qmf);                 // 516 coefficient entries
    dim3 grid(NTILES, NBATCH);
    pqmf_fused_kernel<<<grid, THREADS>>>(x, qmf, y);
}

// round 2
// speedup vs baseline: 1.7342x; 1.7342x over previous
#include <cuda_runtime.h>

#define L_TOT    524288
#define M_TOT    (L_TOT / 4)
#define NBATCH   16
#define TILE     2048
#define NTILES   (L_TOT / TILE)   // 256
#define THREADS  256
#define PH2      616              // float2 per phase; max swz8 index 610

typedef unsigned long long u64;

// combined polyphase filters: C[r][dd], dd = d+64 in [0,128]
__device__ float g_C[4][132];

__device__ __forceinline__ int swz8(int i) { return i + (i >> 3); }

#define FFMA2(acc, a, b) \
    asm("fma.rn.f32x2 %0, %1, %2, %0;" : "+l"(acc) : "l"(a), "l"(b))

__global__ void build_C_kernel(const float* __restrict__ qmf) {
    int idx = blockIdx.x * blockDim.x + threadIdx.x;
    if (idx >= 4 * 129) return;
    int r  = idx / 129;
    int dd = idx % 129;
    int t0 = (4 - r) & 3;
    float sum = 0.f;
    for (int t = t0; t <= 64; t += 4) {
        int s = dd - t;
        if (s >= 0 && s <= 64) {
            #pragma unroll
            for (int k = 0; k < 4; k++)
                sum += qmf[k * 65 + t] * qmf[k * 65 + s];
        }
    }
    g_C[r][dd] = sum;
}

// ---------------- exact two-stage edge kernel (n in [0,32) and [L-32,L)) ----
__global__ void pqmf_edge_kernel(const float* __restrict__ x,
                                 const float* __restrict__ qmf,
                                 float* __restrict__ y) {
    __shared__ float s_q[260];
    __shared__ float s_sub[4][16];
    __shared__ float s_part[128];

    const int side = blockIdx.x;          // 0 = low edge, 1 = high edge
    const int b    = blockIdx.y;
    const float* xb = x + (size_t)b * L_TOT;
    float*       yb = y + (size_t)b * L_TOT;
    const int tid = threadIdx.x;          // 128 threads

    for (int i = tid; i < 260; i += 128) s_q[i] = qmf[i];
    __syncthreads();

    const int mbase = side ? (M_TOT - 16) : 0;
    if (tid < 64) {
        int k = tid & 3, j = tid >> 2;
        int m = mbase + j;
        float sub = 0.f;
        int pbase = 4 * m - 32;
        for (int s = 0; s <= 64; s++) {
            int pos = pbase + s;
            if (pos >= 0 && pos < L_TOT)
                sub = fmaf(s_q[k * 65 + s], xb[pos], sub);
        }
        s_sub[k][j] = sub;
    }
    __syncthreads();

    float partial = 0.f;
    {
        int nn = tid >> 2, k = tid & 3;
        int n  = side ? (L_TOT - 32 + nn) : nn;
        int t0 = (4 - (n & 3)) & 3;
        for (int t = t0; t <= 64; t += 4) {
            int m = (n + t - 32) >> 2;
            if (m < 0 || m >= M_TOT) continue;
            partial = fmaf(s_q[k * 65 + t], s_sub[k][m - mbase], partial);
        }
    }
    s_part[tid] = partial;
    __syncthreads();
    if (tid < 32) {
        int n = side ? (L_TOT - 32 + tid) : tid;
        yb[n] = s_part[tid * 4] + s_part[tid * 4 + 1] +
                s_part[tid * 4 + 2] + s_part[tid * 4 + 3];
    }
}

// ---------------- main kernel: 2 batch rows per block, f32x2 packed ---------
__global__ __launch_bounds__(THREADS)
void pqmf_main2_kernel(const float* __restrict__ x, float* __restrict__ y) {
    __shared__ float2 s_x2[4][PH2];       // phase-split (b0,b1) pairs; reused for y staging
    __shared__ float2 s_C2[4][132];       // duplicated coefficients (c,c)

    const int tile  = blockIdx.x;
    const int tbase = tile * TILE;
    const float* x0 = x + (size_t)(2 * blockIdx.y) * L_TOT;
    const float* x1 = x0 + L_TOT;
    float* y0 = y + (size_t)(2 * blockIdx.y) * L_TOT;
    float* y1 = y0 + L_TOT;

    // load x tile + 64-halo for both batch rows, phase-split + skewed
    for (int idx = threadIdx.x; idx < TILE + 128; idx += THREADS) {
        int pos = tbase - 64 + idx;
        float a = 0.f, bb = 0.f;
        if (pos >= 0 && pos < L_TOT) { a = x0[pos]; bb = x1[pos]; }
        s_x2[idx & 3][swz8(idx >> 2)] = make_float2(a, bb);
    }
    for (int idx = threadIdx.x; idx < 4 * 129; idx += THREADS) {
        float c = g_C[idx / 129][idx % 129];
        s_C2[idx / 129][idx % 129] = make_float2(c, c);
    }
    __syncthreads();

    const int warp   = threadIdx.x >> 5;
    const int lane   = threadIdx.x & 31;
    const int r      = warp & 3;                 // residue owned by this warp
    const int tq     = (warp >> 2) * 32 + lane;  // 0..63
    const int base_q = tq * 8;                   // 8 contiguous outputs/thread

    u64 acc[8];
    #pragma unroll
    for (int j = 0; j < 8; j++) acc[j] = 0ULL;

    #pragma unroll
    for (int f = 0; f < 4; f++) {
        const int E  = (f == 0) ? 33 : 32;
        const int rf = r + f;
        const float2* xr = s_x2[rf & 3];
        const int i0 = base_q + (rf >> 2);

        u64 w[8];
        #pragma unroll
        for (int j = 0; j < 7; j++)
            w[j] = *reinterpret_cast<const u64*>(&xr[swz8(i0 + j)]);

        #pragma unroll
        for (int e = 0; e < 33; e++) {
            if (e < E) {
                u64 c2 = *reinterpret_cast<const u64*>(&s_C2[r][f + 4 * e]);
                w[7] = *reinterpret_cast<const u64*>(&xr[swz8(i0 + e + 7)]);
                #pragma unroll
                for (int j = 0; j < 8; j++) FFMA2(acc[j], c2, w[j]);
                #pragma unroll
                for (int j = 0; j < 7; j++) w[j] = w[j + 1];
            }
        }
    }

    __syncthreads();   // all x reads done: safe to reuse s_x2 as y staging

    #pragma unroll
    for (int j = 0; j < 8; j++)
        *reinterpret_cast<u64*>(&s_x2[r][swz8(base_q + j)]) = acc[j];
    __syncthreads();

    for (int idx = threadIdx.x; idx < TILE; idx += THREADS) {
        int n = tbase + idx;
        float2 v = s_x2[idx & 3][swz8(idx >> 2)];
        if (n >= 32 && n < L_TOT - 32) {   // edges written by edge kernel
            y0[n] = v.x;
            y1[n] = v.y;
        }
    }
}

extern "C" void kernel_launch(void* const* d_in, const int* in_sizes, int n_in,
                              void* d_out, int out_size) {
    const float* x   = (const float*)d_in[0];
    const float* qmf = (const float*)d_in[1];
    if (n_in >= 2 && in_sizes[0] == 260) {
        x   = (const float*)d_in[1];
        qmf = (const float*)d_in[0];
    }
    float* y = (float*)d_out;

    build_C_kernel<<<3, 192>>>(qmf);
    pqmf_edge_kernel<<<dim3(2, NBATCH), 128>>>(x, qmf, y);
    dim3 grid(NTILES, NBATCH / 2);
    pqmf_main2_kernel<<<grid, THREADS>>>(x, y);
}

// round 3
// speedup vs baseline: 2.4903x; 1.4360x over previous
#include <cuda_runtime.h>

#define L_TOT    524288
#define M_TOT    (L_TOT / 4)
#define NBATCH   16
#define TILE     2048
#define NTILES   (L_TOT / TILE)   // 256
#define THREADS  256
#define PH2      616              // float2 per phase; phys max = 7*78+67 = 613

typedef unsigned long long u64;

// combined polyphase filters: C[r][dd], dd = d+64 in [0,128]
__device__ float g_C[4][132];

#define FFMA2(acc, a, b) \
    asm("fma.rn.f32x2 %0, %1, %2, %0;" : "+l"(acc) : "l"(a), "l"(b))

__device__ __forceinline__ int physi(int i) { return (i & 7) * 78 + (i >> 3); }

// ---------------- edge kernel: builds g_C + exact two-stage edges ----------
__global__ void pqmf_edge_kernel(const float* __restrict__ x,
                                 const float* __restrict__ qmf,
                                 float* __restrict__ y) {
    __shared__ float s_q[260];
    __shared__ float s_sub[4][16];
    __shared__ float s_part[128];

    const int side = blockIdx.x;          // 0 = low edge, 1 = high edge
    const int b    = blockIdx.y;
    const float* xb = x + (size_t)b * L_TOT;
    float*       yb = y + (size_t)b * L_TOT;
    const int tid = threadIdx.x;          // 128 threads

    for (int i = tid; i < 260; i += 128) s_q[i] = qmf[i];
    __syncthreads();

    // build combined coefficients (redundant across blocks, identical values;
    // main kernel reads g_C only after this kernel completes — stream order)
    for (int idx = tid; idx < 4 * 129; idx += 128) {
        int r  = idx / 129;
        int dd = idx % 129;
        int t0 = (4 - r) & 3;
        float sum = 0.f;
        for (int t = t0; t <= 64; t += 4) {
            int s = dd - t;
            if (s >= 0 && s <= 64) {
                #pragma unroll
                for (int k = 0; k < 4; k++)
                    sum += s_q[k * 65 + t] * s_q[k * 65 + s];
            }
        }
        g_C[r][dd] = sum;
    }

    const int mbase = side ? (M_TOT - 16) : 0;
    if (tid < 64) {
        int k = tid & 3, j = tid >> 2;
        int m = mbase + j;
        float sub = 0.f;
        int pbase = 4 * m - 32;
        for (int s = 0; s <= 64; s++) {
            int pos = pbase + s;
            if (pos >= 0 && pos < L_TOT)
                sub = fmaf(s_q[k * 65 + s], xb[pos], sub);
        }
        s_sub[k][j] = sub;
    }
    __syncthreads();

    float partial = 0.f;
    {
        int nn = tid >> 2, k = tid & 3;
        int n  = side ? (L_TOT - 32 + nn) : nn;
        int t0 = (4 - (n & 3)) & 3;
        for (int t = t0; t <= 64; t += 4) {
            int m = (n + t - 32) >> 2;
            if (m < 0 || m >= M_TOT) continue;
            partial = fmaf(s_q[k * 65 + t], s_sub[k][m - mbase], partial);
        }
    }
    s_part[tid] = partial;
    __syncthreads();
    if (tid < 32) {
        int n = side ? (L_TOT - 32 + tid) : tid;
        yb[n] = s_part[tid * 4] + s_part[tid * 4 + 1] +
                s_part[tid * 4 + 2] + s_part[tid * 4 + 3];
    }
}

// ---------------- main kernel ------------------------------------------------
// Inner FIR over one phase: all LDS at compile-time immediate offsets.
template<int A, int STEPS>
__device__ __forceinline__ void fir_phase(const float2* __restrict__ B,
                                          const float2* __restrict__ cb,
                                          u64 acc[8]) {
    u64 w[8];
    #pragma unroll
    for (int j = 0; j < 7; j++)
        w[j] = *reinterpret_cast<const u64*>(
            &B[((A + j) & 7) * 78 + ((A + j) >> 3)]);

    #pragma unroll
    for (int e = 0; e < STEPS; e++) {
        u64 c2 = *reinterpret_cast<const u64*>(&cb[e]);
        w[7] = *reinterpret_cast<const u64*>(
            &B[((A + e + 7) & 7) * 78 + ((A + e + 7) >> 3)]);
        #pragma unroll
        for (int j = 0; j < 8; j++) FFMA2(acc[j], c2, w[j]);
        #pragma unroll
        for (int j = 0; j < 7; j++) w[j] = w[j + 1];
    }
}

__global__ __launch_bounds__(THREADS, 3)
void pqmf_main2_kernel(const float* __restrict__ x, float* __restrict__ y) {
    __shared__ float2 s_x2[4][PH2];        // phase-split x (b0,b1); reused for y
    __shared__ float2 s_C2[4][4][33];      // coeffs [r][f][e], duplicated

    const int tile  = blockIdx.x;
    const int tbase = tile * TILE;
    const float* x0 = x + (size_t)(2 * blockIdx.y) * L_TOT;
    const float* x1 = x0 + L_TOT;
    float* y0 = y + (size_t)(2 * blockIdx.y) * L_TOT;
    float* y1 = y0 + L_TOT;

    for (int idx = threadIdx.x; idx < TILE + 128; idx += THREADS) {
        int pos = tbase - 64 + idx;
        float a0 = 0.f, b0 = 0.f;
        if (pos >= 0 && pos < L_TOT) { a0 = x0[pos]; b0 = x1[pos]; }
        s_x2[idx & 3][physi(idx >> 2)] = make_float2(a0, b0);
    }
    for (int idx = threadIdx.x; idx < 4 * 4 * 33; idx += THREADS) {
        int r_  = idx / 132;
        int rem = idx % 132;
        int f_  = rem / 33;
        int e_  = rem % 33;
        int dd  = 4 * e_ + f_;
        float c = (dd <= 128) ? g_C[r_][dd] : 0.f;
        s_C2[r_][f_][e_] = make_float2(c, c);
    }
    __syncthreads();

    const int warp = threadIdx.x >> 5;
    const int lane = threadIdx.x & 31;
    const int r    = warp & 3;                  // residue owned by this warp
    const int tq   = (warp >> 2) * 32 + lane;   // 0..63 per residue

    u64 acc[8];
    #pragma unroll
    for (int j = 0; j < 8; j++) acc[j] = 0ULL;

    // y[r+4q] = sum_dd C[r][dd] * sx[r+4q+dd], dd = 4e+f
    #pragma unroll
    for (int f = 0; f < 4; f++) {
        const int df = r + f;
        const float2* B  = &s_x2[df & 3][tq];
        const float2* cb = s_C2[r][f];
        if (f == 0) {
            // df = r <= 3 -> A = 0 always; dd=128 handled via STEPS=33
            fir_phase<0, 33>(B, cb, acc);
        } else {
            if (df >> 2) fir_phase<1, 32>(B, cb, acc);
            else         fir_phase<0, 32>(B, cb, acc);
        }
    }

    __syncthreads();   // all x reads done: reuse s_x2 as y staging

    #pragma unroll
    for (int j = 0; j < 8; j++)
        *reinterpret_cast<u64*>(&s_x2[r][j * 78 + tq]) = acc[j];
    __syncthreads();

    if (tile > 0 && tile < NTILES - 1) {
        #pragma unroll 4
        for (int idx = threadIdx.x; idx < TILE; idx += THREADS) {
            float2 v = s_x2[idx & 3][physi(idx >> 2)];
            int n = tbase + idx;
            y0[n] = v.x;
            y1[n] = v.y;
        }
    } else {
        for (int idx = threadIdx.x; idx < TILE; idx += THREADS) {
            int n = tbase + idx;
            float2 v = s_x2[idx & 3][physi(idx >> 2)];
            if (n >= 32 && n < L_TOT - 32) {   // edges written by edge kernel
                y0[n] = v.x;
                y1[n] = v.y;
            }
        }
    }
}

extern "C" void kernel_launch(void* const* d_in, const int* in_sizes, int n_in,
                              void* d_out, int out_size) {
    const float* x   = (const float*)d_in[0];
    const float* qmf = (const float*)d_in[1];
    if (n_in >= 2 && in_sizes[0] == 260) {
        x   = (const float*)d_in[1];
        qmf = (const float*)d_in[0];
    }
    float* y = (float*)d_out;

    pqmf_edge_kernel<<<dim3(2, NBATCH), 128>>>(x, qmf, y);
    dim3 grid(NTILES, NBATCH / 2);
    pqmf_main2_kernel<<<grid, THREADS>>>(x, y);
}